// round 7
// baseline (speedup 1.0000x reference)
#include <cuda_runtime.h>
#include <cuda_bf16.h>
#include <stdint.h>
#include <math.h>

#define B_ROWS 8192
#define D 512
#define NTHETA 608
#define NFORE (NTHETA - D)
#define NEXP 8
#define MAXP (B_ROWS * 2)
#define NCHUNK 8              // K=512 / 64
#define BM 256
#define BN 128
#define STG_BYTES 98304       // Ah 32K + Al 32K + Bh 16K + Bl 16K
#define GEMM_SMEM (1024 + 2 * STG_BYTES)

// ---------------- device scratch ----------------
__device__ int   g_count[NEXP];
__device__ int   g_offset[NEXP];
__device__ int   g_cursor[NEXP];
__device__ int   g_token[MAXP];
__device__ int   g_slot[B_ROWS][2];
__device__ float g_gw[B_ROWS][2];

__device__ __nv_bfloat16 g_xh[B_ROWS * D],  g_xl[B_ROWS * D];
__device__ __nv_bfloat16 g_W0h[NEXP * D * D], g_W0l[NEXP * D * D];          // [e][n][k]
__device__ __nv_bfloat16 g_Wmh[3 * NEXP * D * D], g_Wml[3 * NEXP * D * D];  // [l*8+e][n][k]
__device__ __nv_bfloat16 g_Woh[NEXP * NTHETA * D], g_Wol[NEXP * NTHETA * D];// [e][n][k]
__device__ __nv_bfloat16 g_a0h[MAXP * D], g_a0l[MAXP * D];
__device__ __nv_bfloat16 g_a1h[MAXP * D], g_a1l[MAXP * D];
__device__ float g_theta[MAXP * NTHETA];

// ---------------- helpers ----------------
__device__ __forceinline__ uint32_t smem_u32(const void* p) {
    uint32_t a;
    asm("{ .reg .u64 t; cvta.to.shared.u64 t, %1; cvt.u32.u64 %0, t; }" : "=r"(a) : "l"(p));
    return a;
}
__device__ __forceinline__ void cpa16(uint32_t s, const void* g) {
    asm volatile("cp.async.cg.shared.global [%0], [%1], 16;" :: "r"(s), "l"(g) : "memory");
}
__device__ __forceinline__ void ldx4(uint32_t* r, uint32_t addr) {
    asm volatile("ldmatrix.sync.aligned.m8n8.x4.shared.b16 {%0,%1,%2,%3}, [%4];"
                 : "=r"(r[0]), "=r"(r[1]), "=r"(r[2]), "=r"(r[3]) : "r"(addr));
}
__device__ __forceinline__ void mma16816(float* d, const uint32_t* a, const uint32_t* b) {
    asm volatile(
        "mma.sync.aligned.m16n8k16.row.col.f32.bf16.bf16.f32 "
        "{%0,%1,%2,%3}, {%4,%5,%6,%7}, {%8,%9}, {%0,%1,%2,%3};"
        : "+f"(d[0]), "+f"(d[1]), "+f"(d[2]), "+f"(d[3])
        : "r"(a[0]), "r"(a[1]), "r"(a[2]), "r"(a[3]), "r"(b[0]), "r"(b[1]));
}
__device__ __forceinline__ void split2(float v, __nv_bfloat16& h, __nv_bfloat16& l) {
    h = __float2bfloat16(v);
    l = __float2bfloat16(v - __bfloat162float(h));
}

// ---------------- reset ----------------
__global__ void zero_kernel() {
    if (threadIdx.x < NEXP) g_count[threadIdx.x] = 0;
}

// ---------------- gate (also emits hi/lo split of raw x) ----------------
__global__ void gate_kernel(const float* __restrict__ x,
                            const float* __restrict__ gamma,
                            const float* __restrict__ beta,
                            const float* __restrict__ Wg) {
    int row = blockIdx.x;
    const float* xr = x + (size_t)row * D;
    __shared__ float sx[D];
    __shared__ float ws[8], ws2[8];
    __shared__ float smu, srstd;
    __shared__ float logits[NEXP];

    int tid = threadIdx.x;
    float v0 = xr[tid], v1 = xr[tid + 256];
    sx[tid] = v0; sx[tid + 256] = v1;

    // hi/lo split of raw x (consumed by first GEMM)
    {
        __nv_bfloat16 h0, l0, h1, l1;
        split2(v0, h0, l0);
        split2(v1, h1, l1);
        g_xh[(size_t)row * D + tid]       = h0;
        g_xl[(size_t)row * D + tid]       = l0;
        g_xh[(size_t)row * D + tid + 256] = h1;
        g_xl[(size_t)row * D + tid + 256] = l1;
    }

    float s  = v0 + v1;
    float s2 = v0 * v0 + v1 * v1;
    #pragma unroll
    for (int o = 16; o; o >>= 1) {
        s  += __shfl_down_sync(0xFFFFFFFFu, s,  o);
        s2 += __shfl_down_sync(0xFFFFFFFFu, s2, o);
    }
    if ((tid & 31) == 0) { ws[tid >> 5] = s; ws2[tid >> 5] = s2; }
    __syncthreads();
    if (tid == 0) {
        float a = 0.f, b = 0.f;
        #pragma unroll
        for (int i = 0; i < 8; i++) { a += ws[i]; b += ws2[i]; }
        float mu  = a / (float)D;
        float var = b / (float)D - mu * mu;
        smu = mu;
        srstd = rsqrtf(var + 1e-5f);
    }
    __syncthreads();
    float mu = smu, rstd = srstd;

    int e = tid >> 5, lane = tid & 31;
    float acc = 0.f;
    for (int i = lane; i < D; i += 32) {
        float xn = (sx[i] - mu) * rstd * gamma[i] + beta[i];
        acc += xn * Wg[i * NEXP + e];
    }
    #pragma unroll
    for (int o = 16; o; o >>= 1) acc += __shfl_down_sync(0xFFFFFFFFu, acc, o);
    if (lane == 0) logits[e] = acc;
    __syncthreads();

    if (tid == 0) {
        int i0 = 0; float v0l = logits[0];
        #pragma unroll
        for (int i = 1; i < NEXP; i++) if (logits[i] > v0l) { v0l = logits[i]; i0 = i; }
        int i1 = -1; float v1l = -1e30f;
        #pragma unroll
        for (int i = 0; i < NEXP; i++) {
            if (i == i0) continue;
            if (logits[i] > v1l) { v1l = logits[i]; i1 = i; }
        }
        float e1 = __expf(v1l - v0l);
        float inv = 1.f / (1.f + e1);
        g_gw[row][0] = inv;
        g_gw[row][1] = e1 * inv;
        g_slot[row][0] = i0;
        g_slot[row][1] = i1;
        atomicAdd(&g_count[i0], 1);
        atomicAdd(&g_count[i1], 1);
    }
}

__global__ void prefix_kernel() {
    int off = 0;
    for (int e = 0; e < NEXP; e++) {
        g_offset[e] = off;
        g_cursor[e] = off;
        off += g_count[e];
    }
}

__global__ void assign_kernel() {
    int row = blockIdx.x * blockDim.x + threadIdx.x;
    if (row >= B_ROWS) return;
    #pragma unroll
    for (int k = 0; k < 2; k++) {
        int e = g_slot[row][k];
        int p = atomicAdd(&g_cursor[e], 1);
        g_token[p] = row;
        g_slot[row][k] = p;
    }
}

// transpose+split: src [mat][K][N] fp32 -> dst[dsel] [mat][N][K] bf16 hi/lo
__global__ void tsplit_kernel(const float* __restrict__ src, int dsel, int K, int N) {
    __shared__ float t[32][33];
    int mat = blockIdx.z;
    const float* s = src + (size_t)mat * K * N;
    int n0 = blockIdx.x * 32, k0 = blockIdx.y * 32;
    int tx = threadIdx.x, ty = threadIdx.y;   // 32x8
    #pragma unroll
    for (int i = 0; i < 32; i += 8) {
        int k = k0 + ty + i, n = n0 + tx;
        t[ty + i][tx] = (k < K && n < N) ? s[(size_t)k * N + n] : 0.f;
    }
    __syncthreads();
    __nv_bfloat16* dh = (dsel == 0) ? g_W0h : (dsel == 1 ? g_Wmh : g_Woh);
    __nv_bfloat16* dl = (dsel == 0) ? g_W0l : (dsel == 1 ? g_Wml : g_Wol);
    __nv_bfloat16* oh = dh + (size_t)mat * N * K;
    __nv_bfloat16* ol = dl + (size_t)mat * N * K;
    #pragma unroll
    for (int i = 0; i < 32; i += 8) {
        int n = n0 + ty + i, k = k0 + tx;
        if (n < N && k < K) {
            __nv_bfloat16 h, l;
            split2(t[tx][ty + i], h, l);
            oh[(size_t)n * K + k] = h;
            ol[(size_t)n * K + k] = l;
        }
    }
}

// ---------------- HMMA grouped GEMM: 256x128 tile, warp tile 64x64 ----------
// asel: 0 = x (gather via g_token), 1 = a0, 2 = a1
// bsel: 0 = W0, 1..3 = Wmid layer, 4 = Wout
// csel: 0 = a0, 1 = a1, 2 = theta (fp32)
__global__ __launch_bounds__(256, 1)
void moe_gemm(int asel, int bsel, int csel, int Nfull, int relu) {
    extern __shared__ char smem[];
    int e = blockIdx.z;
    int cnt = g_count[e];
    int m0 = blockIdx.y * BM;
    if (m0 >= cnt) return;
    int n0 = blockIdx.x * BN;
    int base = g_offset[e];

    const __nv_bfloat16 *Ah, *Al;
    if (asel == 0)      { Ah = g_xh;  Al = g_xl;  }
    else if (asel == 1) { Ah = g_a0h; Al = g_a0l; }
    else                { Ah = g_a1h; Al = g_a1l; }
    const __nv_bfloat16 *Bh, *Bl;
    if (bsel == 0)      { Bh = g_W0h; Bl = g_W0l; }
    else if (bsel <= 3) {
        size_t off = (size_t)(bsel - 1) * NEXP * D * D;
        Bh = g_Wmh + off; Bl = g_Wml + off;
    } else              { Bh = g_Woh; Bl = g_Wol; }
    int gather = (asel == 0);
    int mode   = (csel == 2);
    __nv_bfloat16* Ch = (csel == 0) ? g_a0h : g_a1h;
    __nv_bfloat16* Cl = (csel == 0) ? g_a0l : g_a1l;

    uint32_t sb = smem_u32(smem);
    uint32_t tiles = (sb + 1023) & ~1023u;

    int tid = threadIdx.x;
    int wid = tid >> 5, lid = tid & 31;
    uint32_t m_warp = (uint32_t)((wid >> 1) * 64);   // 4 m-warps
    uint32_t n_warp = (uint32_t)((wid & 1) * 64);    // 2 n-warps

    // ---- A loader: one 128B row per thread (256 rows) ----
    int am = m0 + tid; if (am >= cnt) am = 0;
    int arow_g = gather ? g_token[base + am] : (base + am);
    const char* pAh = (const char*)Ah + (size_t)arow_g * (D * 2);
    const char* pAl = (const char*)Al + (size_t)arow_g * (D * 2);
    uint32_t axr = (uint32_t)(tid & 7) << 4;
    uint32_t aso = (uint32_t)tid * 128;

    // ---- B loader: one 64B half-row per thread (128 rows) ----
    int brow_l = tid >> 1;
    int bhalf  = (tid & 1) * 64;
    int bn = n0 + brow_l; if (bn >= Nfull) bn = 0;
    const char* pBh = (const char*)(Bh + (size_t)e * Nfull * D) + (size_t)bn * (D * 2) + bhalf;
    const char* pBl = (const char*)(Bl + (size_t)e * Nfull * D) + (size_t)bn * (D * 2) + bhalf;
    uint32_t bxr = (uint32_t)(brow_l & 7) << 4;
    uint32_t bso = (uint32_t)brow_l * 128;

    // ---- ldmatrix lane mapping ----
    int q = lid >> 3, r = lid & 7;
    uint32_t arow_q  = (uint32_t)((q & 1) * 8 + r);
    uint32_t abyte_q = (uint32_t)((q >> 1) * 16);
    uint32_t brow_q  = (uint32_t)((q >> 1) * 8 + r);
    uint32_t bbyte_q = (uint32_t)((q & 1) * 16);
    uint32_t lxor    = (uint32_t)r << 4;

    float acc[4][8][4];
    #pragma unroll
    for (int i = 0; i < 4; i++)
        #pragma unroll
        for (int j = 0; j < 8; j++)
            #pragma unroll
            for (int k = 0; k < 4; k++) acc[i][j][k] = 0.f;

    // ---- prologue: stage 0 ----
    {
        uint32_t st = tiles;
        #pragma unroll
        for (int i = 0; i < 8; i++) {
            uint32_t so = aso + (((uint32_t)(i * 16)) ^ axr);
            cpa16(st +     0 + so, pAh + i * 16);
            cpa16(st + 32768 + so, pAl + i * 16);
        }
        #pragma unroll
        for (int i = 0; i < 4; i++) {
            uint32_t so = bso + (((uint32_t)(bhalf + i * 16)) ^ bxr);
            cpa16(st + 65536 + so, pBh + i * 16);
            cpa16(st + 81920 + so, pBl + i * 16);
        }
        asm volatile("cp.async.commit_group;" ::: "memory");
    }

    #pragma unroll 1
    for (int c = 0; c < NCHUNK; c++) {
        if (c < NCHUNK - 1) {
            uint32_t st = tiles + ((c + 1) & 1) * STG_BYTES;
            size_t goff = (size_t)(c + 1) * 128;
            #pragma unroll
            for (int i = 0; i < 8; i++) {
                uint32_t so = aso + (((uint32_t)(i * 16)) ^ axr);
                cpa16(st +     0 + so, pAh + goff + i * 16);
                cpa16(st + 32768 + so, pAl + goff + i * 16);
            }
            #pragma unroll
            for (int i = 0; i < 4; i++) {
                uint32_t so = bso + (((uint32_t)(bhalf + i * 16)) ^ bxr);
                cpa16(st + 65536 + so, pBh + goff + i * 16);
                cpa16(st + 81920 + so, pBl + goff + i * 16);
            }
            asm volatile("cp.async.commit_group;" ::: "memory");
            asm volatile("cp.async.wait_group 1;" ::: "memory");
        } else {
            asm volatile("cp.async.wait_group 0;" ::: "memory");
        }
        __syncthreads();

        uint32_t st = tiles + (c & 1) * STG_BYTES;
        uint32_t sAh = st, sAl = st + 32768, sBh = st + 65536, sBl = st + 81920;

        #pragma unroll
        for (int kk = 0; kk < 4; kk++) {
            uint32_t bh[16], bl[16];
            #pragma unroll
            for (int g2 = 0; g2 < 4; g2++) {
                uint32_t ro = (n_warp + (uint32_t)(g2 * 16) + brow_q) * 128;
                uint32_t co = ((uint32_t)(kk * 32) + bbyte_q) ^ lxor;
                ldx4(bh + g2 * 4, sBh + ro + co);
                ldx4(bl + g2 * 4, sBl + ro + co);
            }
            #pragma unroll
            for (int mt = 0; mt < 4; mt++) {
                uint32_t ah[4], al[4];
                uint32_t ro = (m_warp + (uint32_t)(mt * 16) + arow_q) * 128;
                uint32_t co = ((uint32_t)(kk * 32) + abyte_q) ^ lxor;
                ldx4(ah, sAh + ro + co);
                ldx4(al, sAl + ro + co);
                #pragma unroll
                for (int nt = 0; nt < 8; nt++) {
                    const uint32_t* bph = bh + (nt >> 1) * 4 + (nt & 1) * 2;
                    const uint32_t* bpl = bl + (nt >> 1) * 4 + (nt & 1) * 2;
                    mma16816(acc[mt][nt], ah, bph);
                    mma16816(acc[mt][nt], ah, bpl);
                    mma16816(acc[mt][nt], al, bph);
                }
            }
        }
        __syncthreads();
    }

    // ---- epilogue ----
    int g = lid >> 2, tig = lid & 3;
    #pragma unroll
    for (int mt = 0; mt < 4; mt++) {
        #pragma unroll
        for (int half = 0; half < 2; half++) {
            int m = m0 + (int)m_warp + mt * 16 + g + half * 8;
            if (m >= cnt) continue;
            size_t orow = (size_t)(base + m);
            #pragma unroll
            for (int nt = 0; nt < 8; nt++) {
                int ncol = n0 + (int)n_warp + nt * 8 + tig * 2;
                float v0 = acc[mt][nt][half * 2 + 0];
                float v1 = acc[mt][nt][half * 2 + 1];
                if (mode == 0) {
                    if (relu) { v0 = fmaxf(v0, 0.f); v1 = fmaxf(v1, 0.f); }
                    __nv_bfloat16 h0, l0, h1, l1;
                    split2(v0, h0, l0);
                    split2(v1, h1, l1);
                    __nv_bfloat162 hp; hp.x = h0; hp.y = h1;
                    __nv_bfloat162 lp; lp.x = l0; lp.y = l1;
                    *(__nv_bfloat162*)(Ch + orow * D + ncol) = hp;
                    *(__nv_bfloat162*)(Cl + orow * D + ncol) = lp;
                } else {
                    if (ncol < NTHETA) {
                        float2 fv; fv.x = v0; fv.y = v1;
                        *(float2*)(g_theta + orow * NTHETA + ncol) = fv;
                    }
                }
            }
        }
    }
}

// ---------------- combine ----------------
__global__ void combine_kernel(float* __restrict__ out) {
    int row = blockIdx.x;
    int p0 = g_slot[row][0], p1 = g_slot[row][1];
    float w0 = g_gw[row][0], w1 = g_gw[row][1];
    const float* t0 = g_theta + (size_t)p0 * NTHETA;
    const float* t1 = g_theta + (size_t)p1 * NTHETA;
    for (int t = threadIdx.x; t < NTHETA; t += blockDim.x) {
        float v = w0 * t0[t] + w1 * t1[t];
        if (t < D) out[(size_t)row * D + t] = v;
        else       out[(size_t)B_ROWS * D + (size_t)row * NFORE + (t - D)] = v;
    }
}

// ---------------- launch ----------------
extern "C" void kernel_launch(void* const* d_in, const int* in_sizes, int n_in,
                              void* d_out, int out_size) {
    const float* x     = (const float*)d_in[0];
    const float* gamma = (const float*)d_in[1];
    const float* beta  = (const float*)d_in[2];
    const float* Wg    = (const float*)d_in[3];
    const float* W0    = (const float*)d_in[4];
    const float* Wmid  = (const float*)d_in[5];
    const float* Wout  = (const float*)d_in[6];
    float* out = (float*)d_out;

    cudaFuncSetAttribute(moe_gemm, cudaFuncAttributeMaxDynamicSharedMemorySize, GEMM_SMEM);

    zero_kernel<<<1, 32>>>();
    gate_kernel<<<B_ROWS, 256>>>(x, gamma, beta, Wg);
    prefix_kernel<<<1, 1>>>();
    assign_kernel<<<B_ROWS / 256, 256>>>();

    dim3 tb(32, 8);
    tsplit_kernel<<<dim3(16, 16, NEXP), tb>>>(W0, 0, D, D);
    tsplit_kernel<<<dim3(16, 16, 3 * NEXP), tb>>>(Wmid, 1, D, D);
    tsplit_kernel<<<dim3(19, 16, NEXP), tb>>>(Wout, 2, D, NTHETA);

    dim3 blk(256);
    dim3 g512(4, 64, NEXP);    // BN=128 -> 4 n-tiles; y=64 covers any routing skew
    dim3 g608(5, 64, NEXP);

    // asel, bsel, csel, Nfull, relu
    moe_gemm<<<g512, blk, GEMM_SMEM>>>(0, 0, 0, D, 0);       // x @ W0      -> a0
    moe_gemm<<<g512, blk, GEMM_SMEM>>>(1, 1, 1, D, 1);       // relu(a0@Wm0)-> a1
    moe_gemm<<<g512, blk, GEMM_SMEM>>>(2, 2, 0, D, 1);       // relu(a1@Wm1)-> a0
    moe_gemm<<<g512, blk, GEMM_SMEM>>>(1, 3, 1, D, 1);       // relu(a0@Wm2)-> a1
    moe_gemm<<<g608, blk, GEMM_SMEM>>>(2, 4, 2, NTHETA, 0);  // a1 @ Wout   -> theta

    combine_kernel<<<B_ROWS, 256>>>(out);
}

// round 8
// speedup vs baseline: 1.4683x; 1.4683x over previous
#include <cuda_runtime.h>
#include <cuda_fp16.h>
#include <stdint.h>
#include <math.h>

#define B_ROWS 8192
#define D 512
#define NTHETA 608
#define NFORE (NTHETA - D)
#define NEXP 8
#define MAXP (B_ROWS * 2)
#define NCHUNK 8              // K=512 / 64
#define BM 128
#define BN 64
#define STG_BYTES 40960       // Ah 16K + Al 16K + Bh 8K
#define GEMM_SMEM (1024 + 2 * STG_BYTES)

// ---------------- device scratch ----------------
__device__ int   g_count[NEXP];
__device__ int   g_offset[NEXP];
__device__ int   g_cursor[NEXP];
__device__ int   g_token[MAXP];
__device__ int   g_slot[B_ROWS][2];
__device__ float g_gw[B_ROWS][2];

__device__ __half g_xh[B_ROWS * D],  g_xl[B_ROWS * D];
__device__ __half g_W0h[NEXP * D * D];            // [e][n][k]  single fp16
__device__ __half g_Wmh[3 * NEXP * D * D];        // [l*8+e][n][k]
__device__ __half g_Woh[NEXP * NTHETA * D];       // [e][n][k]
__device__ __half g_a0h[MAXP * D], g_a0l[MAXP * D];
__device__ __half g_a1h[MAXP * D], g_a1l[MAXP * D];
__device__ float g_theta[MAXP * NTHETA];

// ---------------- helpers ----------------
__device__ __forceinline__ uint32_t smem_u32(const void* p) {
    uint32_t a;
    asm("{ .reg .u64 t; cvta.to.shared.u64 t, %1; cvt.u32.u64 %0, t; }" : "=r"(a) : "l"(p));
    return a;
}
__device__ __forceinline__ void cpa16(uint32_t s, const void* g) {
    asm volatile("cp.async.cg.shared.global [%0], [%1], 16;" :: "r"(s), "l"(g) : "memory");
}
__device__ __forceinline__ void ldx4(uint32_t* r, uint32_t addr) {
    asm volatile("ldmatrix.sync.aligned.m8n8.x4.shared.b16 {%0,%1,%2,%3}, [%4];"
                 : "=r"(r[0]), "=r"(r[1]), "=r"(r[2]), "=r"(r[3]) : "r"(addr));
}
__device__ __forceinline__ void mma16816(float* d, const uint32_t* a, const uint32_t* b) {
    asm volatile(
        "mma.sync.aligned.m16n8k16.row.col.f32.f16.f16.f32 "
        "{%0,%1,%2,%3}, {%4,%5,%6,%7}, {%8,%9}, {%0,%1,%2,%3};"
        : "+f"(d[0]), "+f"(d[1]), "+f"(d[2]), "+f"(d[3])
        : "r"(a[0]), "r"(a[1]), "r"(a[2]), "r"(a[3]), "r"(b[0]), "r"(b[1]));
}
__device__ __forceinline__ void split2h(float v, __half& h, __half& l) {
    h = __float2half(v);
    l = __float2half(v - __half2float(h));
}

// ---------------- reset ----------------
__global__ void zero_kernel() {
    if (threadIdx.x < NEXP) g_count[threadIdx.x] = 0;
}

// ---------------- gate (also emits fp16 hi/lo split of raw x) ----------------
__global__ void gate_kernel(const float* __restrict__ x,
                            const float* __restrict__ gamma,
                            const float* __restrict__ beta,
                            const float* __restrict__ Wg) {
    int row = blockIdx.x;
    const float* xr = x + (size_t)row * D;
    __shared__ float sx[D];
    __shared__ float ws[8], ws2[8];
    __shared__ float smu, srstd;
    __shared__ float logits[NEXP];

    int tid = threadIdx.x;
    float v0 = xr[tid], v1 = xr[tid + 256];
    sx[tid] = v0; sx[tid + 256] = v1;

    {
        __half h0, l0, h1, l1;
        split2h(v0, h0, l0);
        split2h(v1, h1, l1);
        g_xh[(size_t)row * D + tid]       = h0;
        g_xl[(size_t)row * D + tid]       = l0;
        g_xh[(size_t)row * D + tid + 256] = h1;
        g_xl[(size_t)row * D + tid + 256] = l1;
    }

    float s  = v0 + v1;
    float s2 = v0 * v0 + v1 * v1;
    #pragma unroll
    for (int o = 16; o; o >>= 1) {
        s  += __shfl_down_sync(0xFFFFFFFFu, s,  o);
        s2 += __shfl_down_sync(0xFFFFFFFFu, s2, o);
    }
    if ((tid & 31) == 0) { ws[tid >> 5] = s; ws2[tid >> 5] = s2; }
    __syncthreads();
    if (tid == 0) {
        float a = 0.f, b = 0.f;
        #pragma unroll
        for (int i = 0; i < 8; i++) { a += ws[i]; b += ws2[i]; }
        float mu  = a / (float)D;
        float var = b / (float)D - mu * mu;
        smu = mu;
        srstd = rsqrtf(var + 1e-5f);
    }
    __syncthreads();
    float mu = smu, rstd = srstd;

    int e = tid >> 5, lane = tid & 31;
    float acc = 0.f;
    for (int i = lane; i < D; i += 32) {
        float xn = (sx[i] - mu) * rstd * gamma[i] + beta[i];
        acc += xn * Wg[i * NEXP + e];
    }
    #pragma unroll
    for (int o = 16; o; o >>= 1) acc += __shfl_down_sync(0xFFFFFFFFu, acc, o);
    if (lane == 0) logits[e] = acc;
    __syncthreads();

    if (tid == 0) {
        int i0 = 0; float v0l = logits[0];
        #pragma unroll
        for (int i = 1; i < NEXP; i++) if (logits[i] > v0l) { v0l = logits[i]; i0 = i; }
        int i1 = -1; float v1l = -1e30f;
        #pragma unroll
        for (int i = 0; i < NEXP; i++) {
            if (i == i0) continue;
            if (logits[i] > v1l) { v1l = logits[i]; i1 = i; }
        }
        float e1 = __expf(v1l - v0l);
        float inv = 1.f / (1.f + e1);
        g_gw[row][0] = inv;
        g_gw[row][1] = e1 * inv;
        g_slot[row][0] = i0;
        g_slot[row][1] = i1;
        atomicAdd(&g_count[i0], 1);
        atomicAdd(&g_count[i1], 1);
    }
}

__global__ void prefix_kernel() {
    int off = 0;
    for (int e = 0; e < NEXP; e++) {
        g_offset[e] = off;
        g_cursor[e] = off;
        off += g_count[e];
    }
}

__global__ void assign_kernel() {
    int row = blockIdx.x * blockDim.x + threadIdx.x;
    if (row >= B_ROWS) return;
    #pragma unroll
    for (int k = 0; k < 2; k++) {
        int e = g_slot[row][k];
        int p = atomicAdd(&g_cursor[e], 1);
        g_token[p] = row;
        g_slot[row][k] = p;
    }
}

// ---------------- fused weight transpose+convert to fp16 -------------------
// z: 0..7 -> W0 (N=512), 8..31 -> Wmid (N=512), 32..39 -> Wout (N=608)
__global__ void wsplit_kernel(const float* __restrict__ W0,
                              const float* __restrict__ Wmid,
                              const float* __restrict__ Wout) {
    __shared__ float t[32][33];
    int z = blockIdx.z;
    const float* src;
    __half* dst;
    int N;
    if (z < 8)       { src = W0   + (size_t)z * D * D;        dst = g_W0h + (size_t)z * D * D;        N = D; }
    else if (z < 32) { src = Wmid + (size_t)(z - 8) * D * D;  dst = g_Wmh + (size_t)(z - 8) * D * D;  N = D; }
    else             { src = Wout + (size_t)(z - 32) * D * NTHETA;
                       dst = g_Woh + (size_t)(z - 32) * NTHETA * D; N = NTHETA; }

    int n0 = blockIdx.x * 32, k0 = blockIdx.y * 32;
    if (n0 >= N) return;
    int tx = threadIdx.x, ty = threadIdx.y;   // 32x8
    #pragma unroll
    for (int i = 0; i < 32; i += 8) {
        int k = k0 + ty + i, n = n0 + tx;
        t[ty + i][tx] = (n < N) ? src[(size_t)k * N + n] : 0.f;
    }
    __syncthreads();
    #pragma unroll
    for (int i = 0; i < 32; i += 8) {
        int n = n0 + ty + i, k = k0 + tx;
        if (n < N)
            dst[(size_t)n * D + k] = __float2half(t[tx][ty + i]);
    }
}

// ---------------- HMMA grouped GEMM: 128x64 tile, 2-pass fp16 --------------
// asel: 0 = x (gather via g_token), 1 = a0, 2 = a1
// bsel: 0 = W0, 1..3 = Wmid layer, 4 = Wout
// csel: 0 = a0, 1 = a1, 2 = theta (fp32)
__global__ __launch_bounds__(256, 2)
void moe_gemm(int asel, int bsel, int csel, int Nfull, int relu) {
    extern __shared__ char smem[];
    int e = blockIdx.z;
    int cnt = g_count[e];
    int m0 = blockIdx.y * BM;
    if (m0 >= cnt) return;
    int n0 = blockIdx.x * BN;
    if (n0 >= Nfull) return;
    int base = g_offset[e];

    const __half *Ah, *Al;
    if (asel == 0)      { Ah = g_xh;  Al = g_xl;  }
    else if (asel == 1) { Ah = g_a0h; Al = g_a0l; }
    else                { Ah = g_a1h; Al = g_a1l; }
    const __half *Bh;
    if (bsel == 0)      Bh = g_W0h;
    else if (bsel <= 3) Bh = g_Wmh + (size_t)(bsel - 1) * NEXP * D * D;
    else                Bh = g_Woh;
    int gather = (asel == 0);
    int mode   = (csel == 2);
    __half* Ch = (csel == 0) ? g_a0h : g_a1h;
    __half* Cl = (csel == 0) ? g_a0l : g_a1l;

    uint32_t sb = smem_u32(smem);
    uint32_t tiles = (sb + 1023) & ~1023u;

    int tid = threadIdx.x;
    int wid = tid >> 5, lid = tid & 31;
    uint32_t m_warp = (uint32_t)((wid >> 1) * 32);   // 4 m-warps x 32 rows
    uint32_t n_warp = (uint32_t)((wid & 1) * 32);    // 2 n-warps x 32 cols

    // ---- A loader: one 64B half-row per thread (128 rows) ----
    int arow_l = tid >> 1;
    int ahalf  = (tid & 1) * 64;
    int am = m0 + arow_l; if (am >= cnt) am = 0;
    int arow_g = gather ? g_token[base + am] : (base + am);
    const char* pAh = (const char*)Ah + (size_t)arow_g * (D * 2) + ahalf;
    const char* pAl = (const char*)Al + (size_t)arow_g * (D * 2) + ahalf;
    uint32_t axr = (uint32_t)(arow_l & 7) << 4;
    uint32_t aso = (uint32_t)arow_l * 128;

    // ---- B loader: one 32B quarter-row per thread (64 rows) ----
    int brow_l = tid >> 2;
    int bq     = (tid & 3) * 32;
    int bn = n0 + brow_l; if (bn >= Nfull) bn = 0;
    const char* pBh = (const char*)(Bh + (size_t)e * Nfull * D) + (size_t)bn * (D * 2) + bq;
    uint32_t bxr = (uint32_t)(brow_l & 7) << 4;
    uint32_t bso = (uint32_t)brow_l * 128;

    // ---- ldmatrix lane mapping ----
    int q = lid >> 3, r = lid & 7;
    uint32_t arow_q  = (uint32_t)((q & 1) * 8 + r);
    uint32_t abyte_q = (uint32_t)((q >> 1) * 16);
    uint32_t brow_q  = (uint32_t)((q >> 1) * 8 + r);
    uint32_t bbyte_q = (uint32_t)((q & 1) * 16);
    uint32_t lxor    = (uint32_t)r << 4;

    float acc[2][4][4];
    #pragma unroll
    for (int i = 0; i < 2; i++)
        #pragma unroll
        for (int j = 0; j < 4; j++)
            #pragma unroll
            for (int k = 0; k < 4; k++) acc[i][j][k] = 0.f;

    // ---- prologue: stage 0 ----
    {
        uint32_t st = tiles;
        #pragma unroll
        for (int i = 0; i < 4; i++) {
            uint32_t so = aso + (((uint32_t)(ahalf + i * 16)) ^ axr);
            cpa16(st +     0 + so, pAh + i * 16);
            cpa16(st + 16384 + so, pAl + i * 16);
        }
        #pragma unroll
        for (int i = 0; i < 2; i++) {
            uint32_t so = bso + (((uint32_t)(bq + i * 16)) ^ bxr);
            cpa16(st + 32768 + so, pBh + i * 16);
        }
        asm volatile("cp.async.commit_group;" ::: "memory");
    }

    #pragma unroll 1
    for (int c = 0; c < NCHUNK; c++) {
        if (c < NCHUNK - 1) {
            uint32_t st = tiles + ((c + 1) & 1) * STG_BYTES;
            size_t goff = (size_t)(c + 1) * 128;
            #pragma unroll
            for (int i = 0; i < 4; i++) {
                uint32_t so = aso + (((uint32_t)(ahalf + i * 16)) ^ axr);
                cpa16(st +     0 + so, pAh + goff + i * 16);
                cpa16(st + 16384 + so, pAl + goff + i * 16);
            }
            #pragma unroll
            for (int i = 0; i < 2; i++) {
                uint32_t so = bso + (((uint32_t)(bq + i * 16)) ^ bxr);
                cpa16(st + 32768 + so, pBh + goff + i * 16);
            }
            asm volatile("cp.async.commit_group;" ::: "memory");
            asm volatile("cp.async.wait_group 1;" ::: "memory");
        } else {
            asm volatile("cp.async.wait_group 0;" ::: "memory");
        }
        __syncthreads();

        uint32_t st = tiles + (c & 1) * STG_BYTES;
        uint32_t sAh = st, sAl = st + 16384, sBh = st + 32768;

        #pragma unroll
        for (int kk = 0; kk < 4; kk++) {
            uint32_t bh[8];
            #pragma unroll
            for (int g2 = 0; g2 < 2; g2++) {
                uint32_t ro = (n_warp + (uint32_t)(g2 * 16) + brow_q) * 128;
                uint32_t co = ((uint32_t)(kk * 32) + bbyte_q) ^ lxor;
                ldx4(bh + g2 * 4, sBh + ro + co);
            }
            #pragma unroll
            for (int mt = 0; mt < 2; mt++) {
                uint32_t ah[4], al[4];
                uint32_t ro = (m_warp + (uint32_t)(mt * 16) + arow_q) * 128;
                uint32_t co = ((uint32_t)(kk * 32) + abyte_q) ^ lxor;
                ldx4(ah, sAh + ro + co);
                ldx4(al, sAl + ro + co);
                #pragma unroll
                for (int nt = 0; nt < 4; nt++) {
                    const uint32_t* bp = bh + (nt >> 1) * 4 + (nt & 1) * 2;
                    mma16816(acc[mt][nt], ah, bp);
                    mma16816(acc[mt][nt], al, bp);
                }
            }
        }
        __syncthreads();
    }

    // ---- epilogue ----
    int g = lid >> 2, tig = lid & 3;
    #pragma unroll
    for (int mt = 0; mt < 2; mt++) {
        #pragma unroll
        for (int half = 0; half < 2; half++) {
            int m = m0 + (int)m_warp + mt * 16 + g + half * 8;
            if (m >= cnt) continue;
            size_t orow = (size_t)(base + m);
            #pragma unroll
            for (int nt = 0; nt < 4; nt++) {
                int ncol = n0 + (int)n_warp + nt * 8 + tig * 2;
                float v0 = acc[mt][nt][half * 2 + 0];
                float v1 = acc[mt][nt][half * 2 + 1];
                if (mode == 0) {
                    if (relu) { v0 = fmaxf(v0, 0.f); v1 = fmaxf(v1, 0.f); }
                    __half h0, l0, h1, l1;
                    split2h(v0, h0, l0);
                    split2h(v1, h1, l1);
                    __half2 hp; hp.x = h0; hp.y = h1;
                    __half2 lp; lp.x = l0; lp.y = l1;
                    *(__half2*)(Ch + orow * D + ncol) = hp;
                    *(__half2*)(Cl + orow * D + ncol) = lp;
                } else {
                    if (ncol < NTHETA) {
                        float2 fv; fv.x = v0; fv.y = v1;
                        *(float2*)(g_theta + orow * NTHETA + ncol) = fv;
                    }
                }
            }
        }
    }
}

// ---------------- combine ----------------
__global__ void combine_kernel(float* __restrict__ out) {
    int row = blockIdx.x;
    int p0 = g_slot[row][0], p1 = g_slot[row][1];
    float w0 = g_gw[row][0], w1 = g_gw[row][1];
    const float* t0 = g_theta + (size_t)p0 * NTHETA;
    const float* t1 = g_theta + (size_t)p1 * NTHETA;
    for (int t = threadIdx.x; t < NTHETA; t += blockDim.x) {
        float v = w0 * t0[t] + w1 * t1[t];
        if (t < D) out[(size_t)row * D + t] = v;
        else       out[(size_t)B_ROWS * D + (size_t)row * NFORE + (t - D)] = v;
    }
}

// ---------------- launch ----------------
extern "C" void kernel_launch(void* const* d_in, const int* in_sizes, int n_in,
                              void* d_out, int out_size) {
    const float* x     = (const float*)d_in[0];
    const float* gamma = (const float*)d_in[1];
    const float* beta  = (const float*)d_in[2];
    const float* Wg    = (const float*)d_in[3];
    const float* W0    = (const float*)d_in[4];
    const float* Wmid  = (const float*)d_in[5];
    const float* Wout  = (const float*)d_in[6];
    float* out = (float*)d_out;

    cudaFuncSetAttribute(moe_gemm, cudaFuncAttributeMaxDynamicSharedMemorySize, GEMM_SMEM);

    zero_kernel<<<1, 32>>>();
    gate_kernel<<<B_ROWS, 256>>>(x, gamma, beta, Wg);
    prefix_kernel<<<1, 1>>>();
    assign_kernel<<<B_ROWS / 256, 256>>>();

    wsplit_kernel<<<dim3(19, 16, 40), dim3(32, 8)>>>(W0, Wmid, Wout);

    dim3 blk(256);
    dim3 g512(8, 64, NEXP);    // BN=64 -> 8 n-tiles
    dim3 g608(10, 64, NEXP);   // 608 -> 10 n-tiles

    // asel, bsel, csel, Nfull, relu
    moe_gemm<<<g512, blk, GEMM_SMEM>>>(0, 0, 0, D, 0);       // x @ W0      -> a0
    moe_gemm<<<g512, blk, GEMM_SMEM>>>(1, 1, 1, D, 1);       // relu(a0@Wm0)-> a1
    moe_gemm<<<g512, blk, GEMM_SMEM>>>(2, 2, 0, D, 1);       // relu(a1@Wm1)-> a0
    moe_gemm<<<g512, blk, GEMM_SMEM>>>(1, 3, 1, D, 1);       // relu(a0@Wm2)-> a1
    moe_gemm<<<g608, blk, GEMM_SMEM>>>(2, 4, 2, NTHETA, 0);  // a1 @ Wout   -> theta

    combine_kernel<<<B_ROWS, 256>>>(out);
}

// round 10
// speedup vs baseline: 1.7465x; 1.1894x over previous
#include <cuda_runtime.h>
#include <cuda_fp16.h>
#include <stdint.h>
#include <math.h>

#define B_ROWS 8192
#define D 512
#define NTHETA 608
#define NFORE (NTHETA - D)
#define NEXP 8
#define MAXP (B_ROWS * 2)
#define NCHUNK 8              // K=512 / 64
#define BM 128
#define BN 64
#define STG_BYTES 40960       // Ah 16K + Al 16K + Bh 8K
#define GEMM_SMEM (1024 + 2 * STG_BYTES)

// ---------------- device scratch ----------------
__device__ int   g_count[NEXP];
__device__ int   g_offset[NEXP];
__device__ int   g_cursor[NEXP];
__device__ int   g_token[MAXP];
__device__ int   g_slot[B_ROWS][2];
__device__ float g_gw[B_ROWS][2];

__device__ __half g_xh[B_ROWS * D],  g_xl[B_ROWS * D];
__device__ __half g_W0h[NEXP * D * D];            // [e][n][k]  single fp16
__device__ __half g_Wmh[3 * NEXP * D * D];        // [l*8+e][n][k]
__device__ __half g_Woh[NEXP * NTHETA * D];       // [e][n][k]
__device__ __half g_a0h[MAXP * D];                // activations: hi only
__device__ __half g_a1h[MAXP * D];
__device__ float g_theta[MAXP * NTHETA];

// ---------------- helpers ----------------
__device__ __forceinline__ uint32_t smem_u32(const void* p) {
    uint32_t a;
    asm("{ .reg .u64 t; cvta.to.shared.u64 t, %1; cvt.u32.u64 %0, t; }" : "=r"(a) : "l"(p));
    return a;
}
__device__ __forceinline__ void cpa16(uint32_t s, const void* g) {
    asm volatile("cp.async.cg.shared.global [%0], [%1], 16;" :: "r"(s), "l"(g) : "memory");
}
__device__ __forceinline__ void ldx4(uint32_t* r, uint32_t addr) {
    asm volatile("ldmatrix.sync.aligned.m8n8.x4.shared.b16 {%0,%1,%2,%3}, [%4];"
                 : "=r"(r[0]), "=r"(r[1]), "=r"(r[2]), "=r"(r[3]) : "r"(addr));
}
__device__ __forceinline__ void mma16816(float* d, const uint32_t* a, const uint32_t* b) {
    asm volatile(
        "mma.sync.aligned.m16n8k16.row.col.f32.f16.f16.f32 "
        "{%0,%1,%2,%3}, {%4,%5,%6,%7}, {%8,%9}, {%0,%1,%2,%3};"
        : "+f"(d[0]), "+f"(d[1]), "+f"(d[2]), "+f"(d[3])
        : "r"(a[0]), "r"(a[1]), "r"(a[2]), "r"(a[3]), "r"(b[0]), "r"(b[1]));
}
__device__ __forceinline__ void split2h(float v, __half& h, __half& l) {
    h = __float2half(v);
    l = __float2half(v - __half2float(h));
}

// ---------------- reset ----------------
__global__ void zero_kernel() {
    if (threadIdx.x < NEXP) g_count[threadIdx.x] = 0;
}

// ---------------- gate (also emits fp16 hi/lo split of raw x) ----------------
__global__ void gate_kernel(const float* __restrict__ x,
                            const float* __restrict__ gamma,
                            const float* __restrict__ beta,
                            const float* __restrict__ Wg) {
    int row = blockIdx.x;
    const float* xr = x + (size_t)row * D;
    __shared__ float sx[D];
    __shared__ float ws[8], ws2[8];
    __shared__ float smu, srstd;
    __shared__ float logits[NEXP];

    int tid = threadIdx.x;
    float v0 = xr[tid], v1 = xr[tid + 256];
    sx[tid] = v0; sx[tid + 256] = v1;

    {
        __half h0, l0, h1, l1;
        split2h(v0, h0, l0);
        split2h(v1, h1, l1);
        g_xh[(size_t)row * D + tid]       = h0;
        g_xl[(size_t)row * D + tid]       = l0;
        g_xh[(size_t)row * D + tid + 256] = h1;
        g_xl[(size_t)row * D + tid + 256] = l1;
    }

    float s  = v0 + v1;
    float s2 = v0 * v0 + v1 * v1;
    #pragma unroll
    for (int o = 16; o; o >>= 1) {
        s  += __shfl_down_sync(0xFFFFFFFFu, s,  o);
        s2 += __shfl_down_sync(0xFFFFFFFFu, s2, o);
    }
    if ((tid & 31) == 0) { ws[tid >> 5] = s; ws2[tid >> 5] = s2; }
    __syncthreads();
    if (tid == 0) {
        float a = 0.f, b = 0.f;
        #pragma unroll
        for (int i = 0; i < 8; i++) { a += ws[i]; b += ws2[i]; }
        float mu  = a / (float)D;
        float var = b / (float)D - mu * mu;
        smu = mu;
        srstd = rsqrtf(var + 1e-5f);
    }
    __syncthreads();
    float mu = smu, rstd = srstd;

    int e = tid >> 5, lane = tid & 31;
    float acc = 0.f;
    for (int i = lane; i < D; i += 32) {
        float xn = (sx[i] - mu) * rstd * gamma[i] + beta[i];
        acc += xn * Wg[i * NEXP + e];
    }
    #pragma unroll
    for (int o = 16; o; o >>= 1) acc += __shfl_down_sync(0xFFFFFFFFu, acc, o);
    if (lane == 0) logits[e] = acc;
    __syncthreads();

    if (tid == 0) {
        int i0 = 0; float v0l = logits[0];
        #pragma unroll
        for (int i = 1; i < NEXP; i++) if (logits[i] > v0l) { v0l = logits[i]; i0 = i; }
        int i1 = -1; float v1l = -1e30f;
        #pragma unroll
        for (int i = 0; i < NEXP; i++) {
            if (i == i0) continue;
            if (logits[i] > v1l) { v1l = logits[i]; i1 = i; }
        }
        float e1 = __expf(v1l - v0l);
        float inv = 1.f / (1.f + e1);
        g_gw[row][0] = inv;
        g_gw[row][1] = e1 * inv;
        g_slot[row][0] = i0;
        g_slot[row][1] = i1;
        atomicAdd(&g_count[i0], 1);
        atomicAdd(&g_count[i1], 1);
    }
}

__global__ void prefix_kernel() {
    int off = 0;
    for (int e = 0; e < NEXP; e++) {
        g_offset[e] = off;
        g_cursor[e] = off;
        off += g_count[e];
    }
}

__global__ void assign_kernel() {
    int row = blockIdx.x * blockDim.x + threadIdx.x;
    if (row >= B_ROWS) return;
    #pragma unroll
    for (int k = 0; k < 2; k++) {
        int e = g_slot[row][k];
        int p = atomicAdd(&g_cursor[e], 1);
        g_token[p] = row;
        g_slot[row][k] = p;
    }
}

// ---------------- fused weight transpose+convert to fp16 -------------------
// z: 0..7 -> W0 (N=512), 8..31 -> Wmid (N=512), 32..39 -> Wout (N=608)
__global__ void wsplit_kernel(const float* __restrict__ W0,
                              const float* __restrict__ Wmid,
                              const float* __restrict__ Wout) {
    __shared__ float t[32][33];
    int z = blockIdx.z;
    const float* src;
    __half* dst;
    int N;
    if (z < 8)       { src = W0   + (size_t)z * D * D;        dst = g_W0h + (size_t)z * D * D;        N = D; }
    else if (z < 32) { src = Wmid + (size_t)(z - 8) * D * D;  dst = g_Wmh + (size_t)(z - 8) * D * D;  N = D; }
    else             { src = Wout + (size_t)(z - 32) * D * NTHETA;
                       dst = g_Woh + (size_t)(z - 32) * NTHETA * D; N = NTHETA; }

    int n0 = blockIdx.x * 32, k0 = blockIdx.y * 32;
    if (n0 >= N) return;
    int tx = threadIdx.x, ty = threadIdx.y;   // 32x8
    #pragma unroll
    for (int i = 0; i < 32; i += 8) {
        int k = k0 + ty + i, n = n0 + tx;
        t[ty + i][tx] = (n < N) ? src[(size_t)k * N + n] : 0.f;
    }
    __syncthreads();
    #pragma unroll
    for (int i = 0; i < 32; i += 8) {
        int n = n0 + ty + i, k = k0 + tx;
        if (n < N)
            dst[(size_t)n * D + k] = __float2half(t[tx][ty + i]);
    }
}

// ---------------- HMMA grouped GEMM: 128x64 tile ---------------------------
// asel: 0 = x (gather via g_token; 2-pass hi/lo), 1 = a0, 2 = a1 (1-pass)
// bsel: 0 = W0, 1..3 = Wmid layer, 4 = Wout
// csel: 0 = a0, 1 = a1, 2 = theta (fp32)
// apass: 1 or 2 MMA passes over the A operand
__global__ __launch_bounds__(256, 2)
void moe_gemm(int asel, int bsel, int csel, int Nfull, int relu, int apass) {
    extern __shared__ char smem[];
    int e = blockIdx.z;
    int cnt = g_count[e];
    int m0 = blockIdx.y * BM;
    if (m0 >= cnt) return;
    int n0 = blockIdx.x * BN;
    if (n0 >= Nfull) return;
    int base = g_offset[e];

    const __half *Ah, *Al;
    if (asel == 0)      { Ah = g_xh;  Al = g_xl; }
    else if (asel == 1) { Ah = g_a0h; Al = g_a0h; }
    else                { Ah = g_a1h; Al = g_a1h; }
    const __half *Bh;
    if (bsel == 0)      Bh = g_W0h;
    else if (bsel <= 3) Bh = g_Wmh + (size_t)(bsel - 1) * NEXP * D * D;
    else                Bh = g_Woh;
    int gather = (asel == 0);
    int mode   = (csel == 2);
    __half* Ch = (csel == 0) ? g_a0h : g_a1h;

    uint32_t sb = smem_u32(smem);
    uint32_t tiles = (sb + 1023) & ~1023u;

    int tid = threadIdx.x;
    int wid = tid >> 5, lid = tid & 31;
    uint32_t m_warp = (uint32_t)((wid >> 1) * 32);   // 4 m-warps x 32 rows
    uint32_t n_warp = (uint32_t)((wid & 1) * 32);    // 2 n-warps x 32 cols

    // ---- A loader: one 64B half-row per thread (128 rows) ----
    int arow_l = tid >> 1;
    int ahalf  = (tid & 1) * 64;
    int am = m0 + arow_l; if (am >= cnt) am = 0;
    int arow_g = gather ? g_token[base + am] : (base + am);
    const char* pAh = (const char*)Ah + (size_t)arow_g * (D * 2) + ahalf;
    const char* pAl = (const char*)Al + (size_t)arow_g * (D * 2) + ahalf;
    uint32_t axr = (uint32_t)(arow_l & 7) << 4;
    uint32_t aso = (uint32_t)arow_l * 128;

    // ---- B loader: one 32B quarter-row per thread (64 rows) ----
    int brow_l = tid >> 2;
    int bq     = (tid & 3) * 32;
    int bn = n0 + brow_l; if (bn >= Nfull) bn = 0;
    const char* pBh = (const char*)(Bh + (size_t)e * Nfull * D) + (size_t)bn * (D * 2) + bq;
    uint32_t bxr = (uint32_t)(brow_l & 7) << 4;
    uint32_t bso = (uint32_t)brow_l * 128;

    // ---- ldmatrix lane mapping ----
    int q = lid >> 3, r = lid & 7;
    uint32_t arow_q  = (uint32_t)((q & 1) * 8 + r);
    uint32_t abyte_q = (uint32_t)((q >> 1) * 16);
    uint32_t brow_q  = (uint32_t)((q >> 1) * 8 + r);
    uint32_t bbyte_q = (uint32_t)((q & 1) * 16);
    uint32_t lxor    = (uint32_t)r << 4;

    float acc[2][4][4];
    #pragma unroll
    for (int i = 0; i < 2; i++)
        #pragma unroll
        for (int j = 0; j < 4; j++)
            #pragma unroll
            for (int k = 0; k < 4; k++) acc[i][j][k] = 0.f;

    // ---- prologue: stage 0 ----
    {
        uint32_t st = tiles;
        #pragma unroll
        for (int i = 0; i < 4; i++) {
            uint32_t so = aso + (((uint32_t)(ahalf + i * 16)) ^ axr);
            cpa16(st + 0 + so, pAh + i * 16);
            if (apass == 2) cpa16(st + 16384 + so, pAl + i * 16);
        }
        #pragma unroll
        for (int i = 0; i < 2; i++) {
            uint32_t so = bso + (((uint32_t)(bq + i * 16)) ^ bxr);
            cpa16(st + 32768 + so, pBh + i * 16);
        }
        asm volatile("cp.async.commit_group;" ::: "memory");
    }

    #pragma unroll 1
    for (int c = 0; c < NCHUNK; c++) {
        if (c < NCHUNK - 1) {
            uint32_t st = tiles + ((c + 1) & 1) * STG_BYTES;
            size_t goff = (size_t)(c + 1) * 128;
            #pragma unroll
            for (int i = 0; i < 4; i++) {
                uint32_t so = aso + (((uint32_t)(ahalf + i * 16)) ^ axr);
                cpa16(st + 0 + so, pAh + goff + i * 16);
                if (apass == 2) cpa16(st + 16384 + so, pAl + goff + i * 16);
            }
            #pragma unroll
            for (int i = 0; i < 2; i++) {
                uint32_t so = bso + (((uint32_t)(bq + i * 16)) ^ bxr);
                cpa16(st + 32768 + so, pBh + goff + i * 16);
            }
            asm volatile("cp.async.commit_group;" ::: "memory");
            asm volatile("cp.async.wait_group 1;" ::: "memory");
        } else {
            asm volatile("cp.async.wait_group 0;" ::: "memory");
        }
        __syncthreads();

        uint32_t st = tiles + (c & 1) * STG_BYTES;
        uint32_t sAh = st, sAl = st + 16384, sBh = st + 32768;

        #pragma unroll
        for (int kk = 0; kk < 4; kk++) {
            uint32_t bh[8];
            #pragma unroll
            for (int g2 = 0; g2 < 2; g2++) {
                uint32_t ro = (n_warp + (uint32_t)(g2 * 16) + brow_q) * 128;
                uint32_t co = ((uint32_t)(kk * 32) + bbyte_q) ^ lxor;
                ldx4(bh + g2 * 4, sBh + ro + co);
            }
            #pragma unroll
            for (int mt = 0; mt < 2; mt++) {
                uint32_t ah[4];
                uint32_t ro = (m_warp + (uint32_t)(mt * 16) + arow_q) * 128;
                uint32_t co = ((uint32_t)(kk * 32) + abyte_q) ^ lxor;
                ldx4(ah, sAh + ro + co);
                #pragma unroll
                for (int nt = 0; nt < 4; nt++) {
                    const uint32_t* bp = bh + (nt >> 1) * 4 + (nt & 1) * 2;
                    mma16816(acc[mt][nt], ah, bp);
                }
                if (apass == 2) {
                    uint32_t al[4];
                    ldx4(al, sAl + ro + co);
                    #pragma unroll
                    for (int nt = 0; nt < 4; nt++) {
                        const uint32_t* bp = bh + (nt >> 1) * 4 + (nt & 1) * 2;
                        mma16816(acc[mt][nt], al, bp);
                    }
                }
            }
        }
        __syncthreads();
    }

    // ---- epilogue ----
    int g = lid >> 2, tig = lid & 3;
    #pragma unroll
    for (int mt = 0; mt < 2; mt++) {
        #pragma unroll
        for (int half = 0; half < 2; half++) {
            int m = m0 + (int)m_warp + mt * 16 + g + half * 8;
            if (m >= cnt) continue;
            size_t orow = (size_t)(base + m);
            #pragma unroll
            for (int nt = 0; nt < 4; nt++) {
                int ncol = n0 + (int)n_warp + nt * 8 + tig * 2;
                float v0 = acc[mt][nt][half * 2 + 0];
                float v1 = acc[mt][nt][half * 2 + 1];
                if (mode == 0) {
                    if (relu) { v0 = fmaxf(v0, 0.f); v1 = fmaxf(v1, 0.f); }
                    __half2 hp; hp.x = __float2half(v0); hp.y = __float2half(v1);
                    *(__half2*)(Ch + orow * D + ncol) = hp;
                } else {
                    if (ncol < NTHETA) {
                        float2 fv; fv.x = v0; fv.y = v1;
                        *(float2*)(g_theta + orow * NTHETA + ncol) = fv;
                    }
                }
            }
        }
    }
}

// ---------------- combine ----------------
__global__ void combine_kernel(float* __restrict__ out) {
    int row = blockIdx.x;
    int p0 = g_slot[row][0], p1 = g_slot[row][1];
    float w0 = g_gw[row][0], w1 = g_gw[row][1];
    const float* t0 = g_theta + (size_t)p0 * NTHETA;
    const float* t1 = g_theta + (size_t)p1 * NTHETA;
    for (int t = threadIdx.x; t < NTHETA; t += blockDim.x) {
        float v = w0 * t0[t] + w1 * t1[t];
        if (t < D) out[(size_t)row * D + t] = v;
        else       out[(size_t)B_ROWS * D + (size_t)row * NFORE + (t - D)] = v;
    }
}

// ---------------- launch ----------------
extern "C" void kernel_launch(void* const* d_in, const int* in_sizes, int n_in,
                              void* d_out, int out_size) {
    const float* x     = (const float*)d_in[0];
    const float* gamma = (const float*)d_in[1];
    const float* beta  = (const float*)d_in[2];
    const float* Wg    = (const float*)d_in[3];
    const float* W0    = (const float*)d_in[4];
    const float* Wmid  = (const float*)d_in[5];
    const float* Wout  = (const float*)d_in[6];
    float* out = (float*)d_out;

    cudaFuncSetAttribute(moe_gemm, cudaFuncAttributeMaxDynamicSharedMemorySize, GEMM_SMEM);

    zero_kernel<<<1, 32>>>();
    gate_kernel<<<B_ROWS, 256>>>(x, gamma, beta, Wg);
    prefix_kernel<<<1, 1>>>();
    assign_kernel<<<B_ROWS / 256, 256>>>();

    wsplit_kernel<<<dim3(19, 16, 40), dim3(32, 8)>>>(W0, Wmid, Wout);

    dim3 blk(256);
    dim3 g512(8, 64, NEXP);    // BN=64 -> 8 n-tiles
    dim3 g608(10, 64, NEXP);   // 608 -> 10 n-tiles

    // asel, bsel, csel, Nfull, relu, apass
    moe_gemm<<<g512, blk, GEMM_SMEM>>>(0, 0, 0, D, 0, 2);       // x @ W0 (hi+lo) -> a0
    moe_gemm<<<g512, blk, GEMM_SMEM>>>(1, 1, 1, D, 1, 1);       // relu(a0@Wm0)   -> a1
    moe_gemm<<<g512, blk, GEMM_SMEM>>>(2, 2, 0, D, 1, 1);       // relu(a1@Wm1)   -> a0
    moe_gemm<<<g512, blk, GEMM_SMEM>>>(1, 3, 1, D, 1, 1);       // relu(a0@Wm2)   -> a1
    moe_gemm<<<g608, blk, GEMM_SMEM>>>(2, 4, 2, NTHETA, 0, 1);  // a1 @ Wout      -> theta

    combine_kernel<<<B_ROWS, 256>>>(out);
}

// round 12
// speedup vs baseline: 2.2199x; 1.2711x over previous
#include <cuda_runtime.h>
#include <cuda_fp16.h>
#include <stdint.h>
#include <math.h>

#define B_ROWS 8192
#define D 512
#define NTHETA 608
#define NFORE (NTHETA - D)
#define NEXP 8
#define MAXP (B_ROWS * 2)
#define NCHUNK 8              // K=512 / 64
#define BM 128
#define BN 64
#define STG_BYTES 24576       // A 16K + B 8K
#define GEMM_SMEM (1024 + 2 * STG_BYTES)

// ---------------- device scratch ----------------
__device__ int   g_count[NEXP];
__device__ int   g_offset[NEXP];
__device__ int   g_cursor[NEXP];
__device__ int   g_token[MAXP];
__device__ int   g_slot[B_ROWS][2];
__device__ float g_gw[B_ROWS][2];

__device__ __half g_xh[B_ROWS * D];
__device__ __half g_W0h[NEXP * D * D];            // [e][n][k]  fp16
__device__ __half g_Wmh[3 * NEXP * D * D];        // [l*8+e][n][k]
__device__ __half g_Woh[NEXP * NTHETA * D];       // [e][n][k]
__device__ __half g_a0h[MAXP * D];
__device__ __half g_a1h[MAXP * D];
__device__ float g_theta[MAXP * NTHETA];

// ---------------- helpers ----------------
__device__ __forceinline__ uint32_t smem_u32(const void* p) {
    uint32_t a;
    asm("{ .reg .u64 t; cvta.to.shared.u64 t, %1; cvt.u32.u64 %0, t; }" : "=r"(a) : "l"(p));
    return a;
}
__device__ __forceinline__ void cpa16(uint32_t s, const void* g) {
    asm volatile("cp.async.cg.shared.global [%0], [%1], 16;" :: "r"(s), "l"(g) : "memory");
}
__device__ __forceinline__ void ldx4(uint32_t* r, uint32_t addr) {
    asm volatile("ldmatrix.sync.aligned.m8n8.x4.shared.b16 {%0,%1,%2,%3}, [%4];"
                 : "=r"(r[0]), "=r"(r[1]), "=r"(r[2]), "=r"(r[3]) : "r"(addr));
}
__device__ __forceinline__ void mma16816(float* d, const uint32_t* a, const uint32_t* b) {
    asm volatile(
        "mma.sync.aligned.m16n8k16.row.col.f32.f16.f16.f32 "
        "{%0,%1,%2,%3}, {%4,%5,%6,%7}, {%8,%9}, {%0,%1,%2,%3};"
        : "+f"(d[0]), "+f"(d[1]), "+f"(d[2]), "+f"(d[3])
        : "r"(a[0]), "r"(a[1]), "r"(a[2]), "r"(a[3]), "r"(b[0]), "r"(b[1]));
}

// ---------------- reset ----------------
__global__ void zero_kernel() {
    if (threadIdx.x < NEXP) g_count[threadIdx.x] = 0;
}

// ---------------- gate (also emits fp16 x) ----------------
__global__ void gate_kernel(const float* __restrict__ x,
                            const float* __restrict__ gamma,
                            const float* __restrict__ beta,
                            const float* __restrict__ Wg) {
    int row = blockIdx.x;
    const float* xr = x + (size_t)row * D;
    __shared__ float sx[D];
    __shared__ float ws[8], ws2[8];
    __shared__ float smu, srstd;
    __shared__ float logits[NEXP];

    int tid = threadIdx.x;
    float v0 = xr[tid], v1 = xr[tid + 256];
    sx[tid] = v0; sx[tid + 256] = v1;

    g_xh[(size_t)row * D + tid]       = __float2half(v0);
    g_xh[(size_t)row * D + tid + 256] = __float2half(v1);

    float s  = v0 + v1;
    float s2 = v0 * v0 + v1 * v1;
    #pragma unroll
    for (int o = 16; o; o >>= 1) {
        s  += __shfl_down_sync(0xFFFFFFFFu, s,  o);
        s2 += __shfl_down_sync(0xFFFFFFFFu, s2, o);
    }
    if ((tid & 31) == 0) { ws[tid >> 5] = s; ws2[tid >> 5] = s2; }
    __syncthreads();
    if (tid == 0) {
        float a = 0.f, b = 0.f;
        #pragma unroll
        for (int i = 0; i < 8; i++) { a += ws[i]; b += ws2[i]; }
        float mu  = a / (float)D;
        float var = b / (float)D - mu * mu;
        smu = mu;
        srstd = rsqrtf(var + 1e-5f);
    }
    __syncthreads();
    float mu = smu, rstd = srstd;

    int e = tid >> 5, lane = tid & 31;
    float acc = 0.f;
    for (int i = lane; i < D; i += 32) {
        float xn = (sx[i] - mu) * rstd * gamma[i] + beta[i];
        acc += xn * Wg[i * NEXP + e];
    }
    #pragma unroll
    for (int o = 16; o; o >>= 1) acc += __shfl_down_sync(0xFFFFFFFFu, acc, o);
    if (lane == 0) logits[e] = acc;
    __syncthreads();

    if (tid == 0) {
        int i0 = 0; float v0l = logits[0];
        #pragma unroll
        for (int i = 1; i < NEXP; i++) if (logits[i] > v0l) { v0l = logits[i]; i0 = i; }
        int i1 = -1; float v1l = -1e30f;
        #pragma unroll
        for (int i = 0; i < NEXP; i++) {
            if (i == i0) continue;
            if (logits[i] > v1l) { v1l = logits[i]; i1 = i; }
        }
        float e1 = __expf(v1l - v0l);
        float inv = 1.f / (1.f + e1);
        g_gw[row][0] = inv;
        g_gw[row][1] = e1 * inv;
        g_slot[row][0] = i0;
        g_slot[row][1] = i1;
        atomicAdd(&g_count[i0], 1);
        atomicAdd(&g_count[i1], 1);
    }
}

__global__ void prefix_kernel() {
    int off = 0;
    for (int e = 0; e < NEXP; e++) {
        g_offset[e] = off;
        g_cursor[e] = off;
        off += g_count[e];
    }
}

__global__ void assign_kernel() {
    int row = blockIdx.x * blockDim.x + threadIdx.x;
    if (row >= B_ROWS) return;
    #pragma unroll
    for (int k = 0; k < 2; k++) {
        int e = g_slot[row][k];
        int p = atomicAdd(&g_cursor[e], 1);
        g_token[p] = row;
        g_slot[row][k] = p;
    }
}

// ---------------- fused weight transpose+convert to fp16 -------------------
// z: 0..7 -> W0 (N=512), 8..31 -> Wmid (N=512), 32..39 -> Wout (N=608)
__global__ void wsplit_kernel(const float* __restrict__ W0,
                              const float* __restrict__ Wmid,
                              const float* __restrict__ Wout) {
    __shared__ float t[32][33];
    int z = blockIdx.z;
    const float* src;
    __half* dst;
    int N;
    if (z < 8)       { src = W0   + (size_t)z * D * D;        dst = g_W0h + (size_t)z * D * D;        N = D; }
    else if (z < 32) { src = Wmid + (size_t)(z - 8) * D * D;  dst = g_Wmh + (size_t)(z - 8) * D * D;  N = D; }
    else             { src = Wout + (size_t)(z - 32) * D * NTHETA;
                       dst = g_Woh + (size_t)(z - 32) * NTHETA * D; N = NTHETA; }

    int n0 = blockIdx.x * 32, k0 = blockIdx.y * 32;
    if (n0 >= N) return;
    int tx = threadIdx.x, ty = threadIdx.y;   // 32x8
    #pragma unroll
    for (int i = 0; i < 32; i += 8) {
        int k = k0 + ty + i, n = n0 + tx;
        t[ty + i][tx] = (n < N) ? src[(size_t)k * N + n] : 0.f;
    }
    __syncthreads();
    #pragma unroll
    for (int i = 0; i < 32; i += 8) {
        int n = n0 + ty + i, k = k0 + tx;
        if (n < N)
            dst[(size_t)n * D + k] = __float2half(t[tx][ty + i]);
    }
}

// ---------------- HMMA grouped GEMM: 128x64 tile, 1-pass fp16 --------------
// asel: 0 = x (gather via g_token), 1 = a0, 2 = a1
// bsel: 0 = W0, 1..3 = Wmid layer, 4 = Wout
// csel: 0 = a0, 1 = a1, 2 = theta (fp32)
__global__ __launch_bounds__(256, 3)
void moe_gemm(int asel, int bsel, int csel, int Nfull, int relu) {
    extern __shared__ char smem[];
    int e = blockIdx.z;
    int cnt = g_count[e];
    int m0 = blockIdx.y * BM;
    if (m0 >= cnt) return;
    int n0 = blockIdx.x * BN;
    if (n0 >= Nfull) return;
    int base = g_offset[e];

    const __half *Ah;
    if (asel == 0)      Ah = g_xh;
    else if (asel == 1) Ah = g_a0h;
    else                Ah = g_a1h;
    const __half *Bh;
    if (bsel == 0)      Bh = g_W0h;
    else if (bsel <= 3) Bh = g_Wmh + (size_t)(bsel - 1) * NEXP * D * D;
    else                Bh = g_Woh;
    int gather = (asel == 0);
    int mode   = (csel == 2);
    __half* Ch = (csel == 0) ? g_a0h : g_a1h;

    uint32_t sb = smem_u32(smem);
    uint32_t tiles = (sb + 1023) & ~1023u;

    int tid = threadIdx.x;
    int wid = tid >> 5, lid = tid & 31;
    uint32_t m_warp = (uint32_t)((wid >> 1) * 32);   // 4 m-warps x 32 rows
    uint32_t n_warp = (uint32_t)((wid & 1) * 32);    // 2 n-warps x 32 cols

    // ---- A loader: one 64B half-row per thread (128 rows) ----
    int arow_l = tid >> 1;
    int ahalf  = (tid & 1) * 64;
    int am = m0 + arow_l; if (am >= cnt) am = 0;
    int arow_g = gather ? g_token[base + am] : (base + am);
    const char* pAh = (const char*)Ah + (size_t)arow_g * (D * 2) + ahalf;
    uint32_t axr = (uint32_t)(arow_l & 7) << 4;
    uint32_t aso = (uint32_t)arow_l * 128;

    // ---- B loader: one 32B quarter-row per thread (64 rows) ----
    int brow_l = tid >> 2;
    int bq     = (tid & 3) * 32;
    int bn = n0 + brow_l; if (bn >= Nfull) bn = 0;
    const char* pBh = (const char*)(Bh + (size_t)e * Nfull * D) + (size_t)bn * (D * 2) + bq;
    uint32_t bxr = (uint32_t)(brow_l & 7) << 4;
    uint32_t bso = (uint32_t)brow_l * 128;

    // ---- ldmatrix lane mapping ----
    int q = lid >> 3, r = lid & 7;
    uint32_t arow_q  = (uint32_t)((q & 1) * 8 + r);
    uint32_t abyte_q = (uint32_t)((q >> 1) * 16);
    uint32_t brow_q  = (uint32_t)((q >> 1) * 8 + r);
    uint32_t bbyte_q = (uint32_t)((q & 1) * 16);
    uint32_t lxor    = (uint32_t)r << 4;

    float acc[2][4][4];
    #pragma unroll
    for (int i = 0; i < 2; i++)
        #pragma unroll
        for (int j = 0; j < 4; j++)
            #pragma unroll
            for (int k = 0; k < 4; k++) acc[i][j][k] = 0.f;

    // ---- prologue: stage 0 ----
    {
        uint32_t st = tiles;
        #pragma unroll
        for (int i = 0; i < 4; i++) {
            uint32_t so = aso + (((uint32_t)(ahalf + i * 16)) ^ axr);
            cpa16(st + so, pAh + i * 16);
        }
        #pragma unroll
        for (int i = 0; i < 2; i++) {
            uint32_t so = bso + (((uint32_t)(bq + i * 16)) ^ bxr);
            cpa16(st + 16384 + so, pBh + i * 16);
        }
        asm volatile("cp.async.commit_group;" ::: "memory");
    }

    #pragma unroll 1
    for (int c = 0; c < NCHUNK; c++) {
        if (c < NCHUNK - 1) {
            uint32_t st = tiles + ((c + 1) & 1) * STG_BYTES;
            size_t goff = (size_t)(c + 1) * 128;
            #pragma unroll
            for (int i = 0; i < 4; i++) {
                uint32_t so = aso + (((uint32_t)(ahalf + i * 16)) ^ axr);
                cpa16(st + so, pAh + goff + i * 16);
            }
            #pragma unroll
            for (int i = 0; i < 2; i++) {
                uint32_t so = bso + (((uint32_t)(bq + i * 16)) ^ bxr);
                cpa16(st + 16384 + so, pBh + goff + i * 16);
            }
            asm volatile("cp.async.commit_group;" ::: "memory");
            asm volatile("cp.async.wait_group 1;" ::: "memory");
        } else {
            asm volatile("cp.async.wait_group 0;" ::: "memory");
        }
        __syncthreads();

        uint32_t st = tiles + (c & 1) * STG_BYTES;
        uint32_t sAh = st, sBh = st + 16384;

        #pragma unroll
        for (int kk = 0; kk < 4; kk++) {
            uint32_t bh[8];
            #pragma unroll
            for (int g2 = 0; g2 < 2; g2++) {
                uint32_t ro = (n_warp + (uint32_t)(g2 * 16) + brow_q) * 128;
                uint32_t co = ((uint32_t)(kk * 32) + bbyte_q) ^ lxor;
                ldx4(bh + g2 * 4, sBh + ro + co);
            }
            #pragma unroll
            for (int mt = 0; mt < 2; mt++) {
                uint32_t ah[4];
                uint32_t ro = (m_warp + (uint32_t)(mt * 16) + arow_q) * 128;
                uint32_t co = ((uint32_t)(kk * 32) + abyte_q) ^ lxor;
                ldx4(ah, sAh + ro + co);
                #pragma unroll
                for (int nt = 0; nt < 4; nt++) {
                    const uint32_t* bp = bh + (nt >> 1) * 4 + (nt & 1) * 2;
                    mma16816(acc[mt][nt], ah, bp);
                }
            }
        }
        __syncthreads();
    }

    // ---- epilogue ----
    int g = lid >> 2, tig = lid & 3;
    #pragma unroll
    for (int mt = 0; mt < 2; mt++) {
        #pragma unroll
        for (int half = 0; half < 2; half++) {
            int m = m0 + (int)m_warp + mt * 16 + g + half * 8;
            if (m >= cnt) continue;
            size_t orow = (size_t)(base + m);
            #pragma unroll
            for (int nt = 0; nt < 4; nt++) {
                int ncol = n0 + (int)n_warp + nt * 8 + tig * 2;
                float v0 = acc[mt][nt][half * 2 + 0];
                float v1 = acc[mt][nt][half * 2 + 1];
                if (mode == 0) {
                    if (relu) { v0 = fmaxf(v0, 0.f); v1 = fmaxf(v1, 0.f); }
                    __half2 hp; hp.x = __float2half(v0); hp.y = __float2half(v1);
                    *(__half2*)(Ch + orow * D + ncol) = hp;
                } else {
                    if (ncol < NTHETA) {
                        float2 fv; fv.x = v0; fv.y = v1;
                        *(float2*)(g_theta + orow * NTHETA + ncol) = fv;
                    }
                }
            }
        }
    }
}

// ---------------- combine ----------------
__global__ void combine_kernel(float* __restrict__ out) {
    int row = blockIdx.x;
    int p0 = g_slot[row][0], p1 = g_slot[row][1];
    float w0 = g_gw[row][0], w1 = g_gw[row][1];
    const float* t0 = g_theta + (size_t)p0 * NTHETA;
    const float* t1 = g_theta + (size_t)p1 * NTHETA;
    for (int t = threadIdx.x; t < NTHETA; t += blockDim.x) {
        float v = w0 * t0[t] + w1 * t1[t];
        if (t < D) out[(size_t)row * D + t] = v;
        else       out[(size_t)B_ROWS * D + (size_t)row * NFORE + (t - D)] = v;
    }
}

// ---------------- launch ----------------
extern "C" void kernel_launch(void* const* d_in, const int* in_sizes, int n_in,
                              void* d_out, int out_size) {
    const float* x     = (const float*)d_in[0];
    const float* gamma = (const float*)d_in[1];
    const float* beta  = (const float*)d_in[2];
    const float* Wg    = (const float*)d_in[3];
    const float* W0    = (const float*)d_in[4];
    const float* Wmid  = (const float*)d_in[5];
    const float* Wout  = (const float*)d_in[6];
    float* out = (float*)d_out;

    cudaFuncSetAttribute(moe_gemm, cudaFuncAttributeMaxDynamicSharedMemorySize, GEMM_SMEM);

    zero_kernel<<<1, 32>>>();
    gate_kernel<<<B_ROWS, 256>>>(x, gamma, beta, Wg);
    prefix_kernel<<<1, 1>>>();
    assign_kernel<<<B_ROWS / 256, 256>>>();

    wsplit_kernel<<<dim3(19, 16, 40), dim3(32, 8)>>>(W0, Wmid, Wout);

    dim3 blk(256);
    dim3 g512(8, 64, NEXP);    // BN=64 -> 8 n-tiles
    dim3 g608(10, 64, NEXP);   // 608 -> 10 n-tiles

    // asel, bsel, csel, Nfull, relu
    moe_gemm<<<g512, blk, GEMM_SMEM>>>(0, 0, 0, D, 0);       // x @ W0       -> a0
    moe_gemm<<<g512, blk, GEMM_SMEM>>>(1, 1, 1, D, 1);       // relu(a0@Wm0) -> a1
    moe_gemm<<<g512, blk, GEMM_SMEM>>>(2, 2, 0, D, 1);       // relu(a1@Wm1) -> a0
    moe_gemm<<<g512, blk, GEMM_SMEM>>>(1, 3, 1, D, 1);       // relu(a0@Wm2) -> a1
    moe_gemm<<<g608, blk, GEMM_SMEM>>>(2, 4, 2, NTHETA, 0);  // a1 @ Wout    -> theta

    combine_kernel<<<B_ROWS, 256>>>(out);
}